// round 2
// baseline (speedup 1.0000x reference)
#include <cuda_runtime.h>

// LookupFreeQuantizer — sm_103a
// Math: softmax over 1024 sign-codes factorizes into 10 independent bits.
//   p(bit_c=+1) = sigmoid(400*z_c)
//   per_sample_entropy = sum_c BinaryEntropy(p_c)        (exact)
//   probs[n] = prod_c p_c(bit_n_c)  -> needed only for avg_probs (eps inside log)
// Output layout (fp32): [ z_q 655360 | loss, commit, ent_loss, pse, avg_ent | indices 65536 ]

#define CH      10
#define HW      1024
#define NSAMP   65536
#define NELEM   655360
#define OUT_SCALARS 655360
#define OUT_IDX     655365

__device__ float  g_avg[1024];
__device__ double g_ent;
__device__ double g_commit;

__global__ void zero_kernel() {
    int i = threadIdx.x;
    g_avg[i] = 0.f;
    if (i == 0) { g_ent = 0.0; g_commit = 0.0; }
}

// Elementwise sign -> z_q output, plus commitment-loss sum reduction.
__global__ void sign_commit_kernel(const float* __restrict__ z, float* __restrict__ out) {
    int i = blockIdx.x * blockDim.x + threadIdx.x;
    int stride = gridDim.x * blockDim.x;
    float local = 0.f;
    for (int j = i; j < NELEM; j += stride) {
        float v = z[j];
        float s = v > 0.f ? 1.f : -1.f;
        out[j] = s;
        float d = s - v;
        local = fmaf(d, d, local);
    }
    #pragma unroll
    for (int o = 16; o; o >>= 1) local += __shfl_down_sync(0xffffffffu, local, o);
    __shared__ float ws[32];
    int lane = threadIdx.x & 31, w = threadIdx.x >> 5;
    if (lane == 0) ws[w] = local;
    __syncthreads();
    if (w == 0) {
        local = (lane < (int)(blockDim.x >> 5)) ? ws[lane] : 0.f;
        #pragma unroll
        for (int o = 16; o; o >>= 1) local += __shfl_down_sync(0xffffffffu, local, o);
        if (lane == 0) atomicAdd(&g_commit, (double)local);
    }
}

// Warp-per-sample: entropy + index + factorized prob accumulation.
// Lane owns codebook bins n = k*32 + lane (k = 0..31):
//   low 5 bits of n  = lane bits  -> scalar lowFactor per lane
//   high 5 bits of n = k bits     -> 32-entry register product tree (unrolled)
__global__ void __launch_bounds__(256, 2)
sample_kernel(const float* __restrict__ z, float* __restrict__ out) {
    const int lane = threadIdx.x & 31;
    const int gw   = (blockIdx.x * blockDim.x + threadIdx.x) >> 5;
    const int nw   = (gridDim.x * blockDim.x) >> 5;

    float acc[32];
    #pragma unroll
    for (int k = 0; k < 32; k++) acc[k] = 0.f;
    float entAcc = 0.f;

    for (int s = gw; s < NSAMP; s += nw) {
        const float* zp = z + ((s >> 10) * (CH * HW)) + (s & (HW - 1));
        float p1[CH], p0[CH];
        float Hs = 0.f;
        int idx = 0;
        #pragma unroll
        for (int c = 0; c < CH; c++) {
            float zv = __ldg(zp + c * HW);   // warp-uniform broadcast load
            float t  = 400.f * zv;
            float a  = fabsf(t);
            float e  = __expf(-a);           // e^{-|400 z|}
            float pmaj, pmin, H;
            if (e < 1e-6f) {                 // warp-uniform branch, ~97% of channels
                pmaj = 1.f - e; pmin = e;
                H = e * (1.f + a);           // log1p(e)~e, a*pmin~a*e  (err < 1e-12)
            } else {
                pmaj = __fdividef(1.f, 1.f + e);
                pmin = e * pmaj;
                H = log1pf(e) + a * pmin;    // exact binary entropy
            }
            bool pos = t > 0.f;
            p1[c] = pos ? pmaj : pmin;
            p0[c] = pos ? pmin : pmaj;
            idx |= pos ? (1 << c) : 0;
            Hs += H;
        }
        if (lane == 0) {
            entAcc += Hs;
            out[OUT_IDX + s] = (float)idx;
        }
        // low-factor: channels 0..4 selected by lane bits
        float f = (lane & 1)  ? p1[0] : p0[0];
        f *= (lane & 2)  ? p1[1] : p0[1];
        f *= (lane & 4)  ? p1[2] : p0[2];
        f *= (lane & 8)  ? p1[3] : p0[3];
        f *= (lane & 16) ? p1[4] : p0[4];
        // high-factor product tree over channels 5..9 (bit j of k <-> channel 5+j)
        float hp[32];
        hp[0] = p0[5]; hp[1] = p1[5];
        #pragma unroll
        for (int j = 1; j < 5; j++) {
            const int sz = 1 << j;
            #pragma unroll
            for (int m = sz - 1; m >= 0; m--) {
                hp[m + sz] = hp[m] * p1[5 + j];
                hp[m]      = hp[m] * p0[5 + j];
            }
        }
        #pragma unroll
        for (int k = 0; k < 32; k++) acc[k] = fmaf(hp[k], f, acc[k]);
    }

    #pragma unroll
    for (int k = 0; k < 32; k++) atomicAdd(&g_avg[k * 32 + lane], acc[k]);
    if (lane == 0) atomicAdd(&g_ent, (double)entAcc);
}

// avg_entropy + scalar outputs. One block of 1024 threads.
__global__ void finalize_kernel(float* __restrict__ out) {
    int n = threadIdx.x;
    float p = g_avg[n] * (1.f / 65536.f);
    float term = p * logf(p + 1e-5f);
    #pragma unroll
    for (int o = 16; o; o >>= 1) term += __shfl_down_sync(0xffffffffu, term, o);
    __shared__ float ws[32];
    if ((n & 31) == 0) ws[n >> 5] = term;
    __syncthreads();
    if (n < 32) {
        float v = ws[n];
        #pragma unroll
        for (int o = 16; o; o >>= 1) v += __shfl_down_sync(0xffffffffu, v, o);
        if (n == 0) {
            float pse         = (float)(g_ent / 65536.0);
            float avg_entropy = -v;                       // ENT_GAMMA = 1.0
            float entropy_loss = 0.1f * (pse - avg_entropy);
            float commitment   = 0.25f * (float)(g_commit / 655360.0);
            out[OUT_SCALARS + 0] = commitment + entropy_loss;  // loss
            out[OUT_SCALARS + 1] = commitment;
            out[OUT_SCALARS + 2] = entropy_loss;
            out[OUT_SCALARS + 3] = pse;
            out[OUT_SCALARS + 4] = avg_entropy;
        }
    }
}

extern "C" void kernel_launch(void* const* d_in, const int* in_sizes, int n_in,
                              void* d_out, int out_size) {
    const float* z = (const float*)d_in[0];
    float* out = (float*)d_out;
    zero_kernel<<<1, 1024>>>();
    sign_commit_kernel<<<640, 256>>>(z, out);
    sample_kernel<<<296, 256>>>(z, out);
    finalize_kernel<<<1, 1024>>>(out);
}

// round 3
// speedup vs baseline: 4.8954x; 4.8954x over previous
#include <cuda_runtime.h>

// LookupFreeQuantizer — sm_103a, round 2
// Factorized softmax: p(bit_c=+1) = sigmoid(400 z_c).
//   per_sample_entropy = sum_c BinaryEntropy  (exact)
//   probs[n] = P0 * prod_{c in flipset} e_c,  e_c = exp(-400|z_c|), P0 = prod 1/(1+e_c)
// Sparse scatter: only subsets of channels with e_c > 1e-7 carry mass > 1e-7
// (neglected mass <= 1e-6 per sample -> avg_entropy abs error ~1e-5, << 1e-3 gate).
// Output layout (fp32): [ z_q 655360 | loss, commit, ent_loss, pse, avg_ent | indices 65536 ]

#define CH      10
#define HW      1024
#define NSAMP   65536
#define NELEM   655360
#define OUT_SCALARS 655360
#define OUT_IDX     655365
#define THRESH  1e-7f

__device__ float  g_avg[1024];
__device__ double g_ent;
__device__ double g_commit;

__global__ void zero_kernel() {
    int i = threadIdx.x;
    g_avg[i] = 0.f;
    if (i == 0) { g_ent = 0.0; g_commit = 0.0; }
}

// Thread-per-sample fused kernel: z_q + commitment + entropy + indices + sparse probs.
__global__ void __launch_bounds__(256)
main_kernel(const float* __restrict__ z, float* __restrict__ out) {
    int s0 = blockIdx.x * blockDim.x + threadIdx.x;
    int stride = gridDim.x * blockDim.x;
    float entAcc = 0.f, comAcc = 0.f;

    for (int s = s0; s < NSAMP; s += stride) {
        const int base = (s >> 10) * (CH * HW) + (s & (HW - 1));
        const float* zp = z + base;
        float* op = out + base;

        float eloc[CH];           // local array, read dynamically only on rare soft path
        float P0 = 1.f, Hs = 0.f;
        int idx = 0;
        unsigned m = 0;

        #pragma unroll
        for (int c = 0; c < CH; c++) {
            float v = zp[c * HW];                 // coalesced: lanes -> consecutive floats
            bool pos = v > 0.f;
            float sgn = pos ? 1.f : -1.f;
            op[c * HW] = sgn;                     // z_q (sign), coalesced
            float d = sgn - v;
            comAcc = fmaf(d, d, comAcc);
            float a = 400.f * fabsf(v);
            float ec = __expf(-a);
            eloc[c] = ec;
            float pmaj, H;
            if (ec > THRESH) {                    // rare (~3% per channel)
                pmaj = __fdividef(1.f, 1.f + ec);
                H = log1pf(ec) + a * ec * pmaj;   // exact binary entropy
                m |= (1u << c);
            } else {
                pmaj = 1.f - ec;
                H = ec * (1.f + a);               // 1st-order, err < 1e-12
            }
            P0 *= pmaj;
            Hs += H;
            if (pos) idx |= (1 << c);
        }

        entAcc += Hs;
        out[OUT_IDX + s] = (float)idx;            // coalesced

        // Sparse prob scatter: all submasks of the soft set m (incl. empty).
        unsigned sub = m;
        for (;;) {
            float w = P0;
            unsigned tt = sub;
            while (tt) {                          // prod of e_c over flipped bits
                int c = __ffs(tt) - 1;
                tt &= tt - 1;
                w *= eloc[c];
            }
            atomicAdd(&g_avg[idx ^ (int)sub], w); // compiles to RED.F32 (no return)
            if (!sub) break;
            sub = (sub - 1) & m;
        }
    }

    // block reduction of entropy + commitment -> 2 double atomics per block
    #pragma unroll
    for (int o = 16; o; o >>= 1) {
        entAcc += __shfl_down_sync(0xffffffffu, entAcc, o);
        comAcc += __shfl_down_sync(0xffffffffu, comAcc, o);
    }
    __shared__ float we[8], wc[8];
    int lane = threadIdx.x & 31, w = threadIdx.x >> 5;
    if (lane == 0) { we[w] = entAcc; wc[w] = comAcc; }
    __syncthreads();
    if (w == 0) {
        float e2 = (lane < (int)(blockDim.x >> 5)) ? we[lane] : 0.f;
        float c2 = (lane < (int)(blockDim.x >> 5)) ? wc[lane] : 0.f;
        #pragma unroll
        for (int o = 4; o; o >>= 1) {
            e2 += __shfl_down_sync(0xffffffffu, e2, o);
            c2 += __shfl_down_sync(0xffffffffu, c2, o);
        }
        if (lane == 0) {
            atomicAdd(&g_ent, (double)e2);
            atomicAdd(&g_commit, (double)c2);
        }
    }
}

// avg_entropy + the 5 scalar outputs. One block of 1024 threads.
__global__ void finalize_kernel(float* __restrict__ out) {
    int n = threadIdx.x;
    float p = g_avg[n] * (1.f / 65536.f);
    float term = p * logf(p + 1e-5f);
    #pragma unroll
    for (int o = 16; o; o >>= 1) term += __shfl_down_sync(0xffffffffu, term, o);
    __shared__ float ws[32];
    if ((n & 31) == 0) ws[n >> 5] = term;
    __syncthreads();
    if (n < 32) {
        float v = ws[n];
        #pragma unroll
        for (int o = 16; o; o >>= 1) v += __shfl_down_sync(0xffffffffu, v, o);
        if (n == 0) {
            float pse          = (float)(g_ent / 65536.0);
            float avg_entropy  = -v;                        // ENT_GAMMA = 1.0
            float entropy_loss = 0.1f * (pse - avg_entropy);
            float commitment   = 0.25f * (float)(g_commit / 655360.0);
            out[OUT_SCALARS + 0] = commitment + entropy_loss;  // loss
            out[OUT_SCALARS + 1] = commitment;
            out[OUT_SCALARS + 2] = entropy_loss;
            out[OUT_SCALARS + 3] = pse;
            out[OUT_SCALARS + 4] = avg_entropy;
        }
    }
}

extern "C" void kernel_launch(void* const* d_in, const int* in_sizes, int n_in,
                              void* d_out, int out_size) {
    const float* z = (const float*)d_in[0];
    float* out = (float*)d_out;
    zero_kernel<<<1, 1024>>>();
    main_kernel<<<256, 256>>>(z, out);
    finalize_kernel<<<1, 1024>>>(out);
}

// round 5
// speedup vs baseline: 5.5616x; 1.1361x over previous
#include <cuda_runtime.h>

// LookupFreeQuantizer — sm_103a, round 3: single self-resetting fused kernel.
// Factorized softmax: p(bit_c=+1) = sigmoid(400 z_c).
//   per_sample_entropy = sum_c BinaryEntropy  (exact)
//   probs[n] = P0 * prod_{c in flipset} e_c,  e_c = exp(-400|z_c|), P0 = prod 1/(1+e_c)
// Sparse scatter: only subsets of channels with e_c > 1e-7 carry mass > 1e-7
// (neglected mass <= 1e-6/sample -> avg_entropy abs err ~1e-5, << 1e-3 gate).
// Output layout (fp32): [ z_q 655360 | loss, commit, ent_loss, pse, avg_ent | indices 65536 ]

#define CH      10
#define HW      1024
#define NSAMP   65536
#define OUT_SCALARS 655360
#define OUT_IDX     655365
#define THRESH  1e-7f
#define NBLK    128
#define NTHR    512

// Zero-initialized at module load; last block re-zeroes after use -> replay-safe.
__device__ float        g_avg[1024];
__device__ double       g_ent;
__device__ double       g_commit;
__device__ unsigned int g_count;

__global__ void __launch_bounds__(NTHR)
fused_kernel(const float* __restrict__ z, float* __restrict__ out) {
    __shared__ float bins[1024];
    __shared__ float we[16], wc[16];
    __shared__ bool  isLast;

    const int tid  = threadIdx.x;
    const int lane = tid & 31;
    const int wrp  = tid >> 5;
    const int s    = blockIdx.x * NTHR + tid;      // one sample per thread

    bins[tid] = 0.f; bins[tid + 512] = 0.f;
    __syncthreads();

    // ---- per-sample math ----
    const int base = (s >> 10) * (CH * HW) + (s & (HW - 1));
    const float* zp = z + base;
    float* op = out + base;

    float eloc[CH];
    float P0 = 1.f, Hs = 0.f, comAcc = 0.f;
    int idx = 0;
    unsigned m = 0;

    #pragma unroll
    for (int c = 0; c < CH; c++) {
        float v = zp[c * HW];                      // coalesced
        bool pos = v > 0.f;
        float sgn = pos ? 1.f : -1.f;
        op[c * HW] = sgn;                          // z_q
        float d = sgn - v;
        comAcc = fmaf(d, d, comAcc);
        float a = 400.f * fabsf(v);
        float ec = __expf(-a);
        eloc[c] = ec;
        float pmaj, H;
        if (ec > THRESH) {                         // rare (~3%/channel)
            pmaj = __fdividef(1.f, 1.f + ec);
            H = log1pf(ec) + a * ec * pmaj;        // exact binary entropy
            m |= (1u << c);
        } else {
            pmaj = 1.f - ec;
            H = ec * (1.f + a);                    // 1st-order, err < 1e-12
        }
        P0 *= pmaj;
        Hs += H;
        if (pos) idx |= (1 << c);
    }
    out[OUT_IDX + s] = (float)idx;

    // ---- sparse prob scatter into shared histogram ----
    unsigned sub = m;
    for (;;) {
        float w = P0;
        unsigned tt = sub;
        while (tt) {
            int c = __ffs(tt) - 1;
            tt &= tt - 1;
            w *= eloc[c];
        }
        atomicAdd(&bins[idx ^ (int)sub], w);
        if (!sub) break;
        sub = (sub - 1) & m;
    }

    // ---- block reduce entropy + commitment ----
    float entAcc = Hs;
    #pragma unroll
    for (int o = 16; o; o >>= 1) {
        entAcc += __shfl_down_sync(0xffffffffu, entAcc, o);
        comAcc += __shfl_down_sync(0xffffffffu, comAcc, o);
    }
    if (lane == 0) { we[wrp] = entAcc; wc[wrp] = comAcc; }
    __syncthreads();
    if (wrp == 0) {
        float e2 = (lane < 16) ? we[lane] : 0.f;
        float c2 = (lane < 16) ? wc[lane] : 0.f;
        #pragma unroll
        for (int o = 8; o; o >>= 1) {
            e2 += __shfl_down_sync(0xffffffffu, e2, o);
            c2 += __shfl_down_sync(0xffffffffu, c2, o);
        }
        if (lane == 0) {
            atomicAdd(&g_ent, (double)e2);
            atomicAdd(&g_commit, (double)c2);
        }
    }

    // ---- drain nonzero bins to global (RED.F32, no return) ----
    {
        float v0 = bins[tid], v1 = bins[tid + 512];
        if (v0 != 0.f) atomicAdd(&g_avg[tid],       v0);
        if (v1 != 0.f) atomicAdd(&g_avg[tid + 512], v1);
    }

    // ---- last-block finalize (self-resetting accumulators) ----
    __threadfence();
    __syncthreads();
    if (tid == 0)
        isLast = (atomicAdd(&g_count, 1u) == (unsigned)(gridDim.x - 1));
    __syncthreads();
    if (!isLast) return;
    __threadfence();

    // avg_entropy = -sum p*log(p+1e-5), p = g_avg/65536
    float p0 = __ldcg(&g_avg[tid])       * (1.f / 65536.f);
    float p1 = __ldcg(&g_avg[tid + 512]) * (1.f / 65536.f);
    float term = p0 * logf(p0 + 1e-5f) + p1 * logf(p1 + 1e-5f);
    #pragma unroll
    for (int o = 16; o; o >>= 1) term += __shfl_down_sync(0xffffffffu, term, o);
    if (lane == 0) we[wrp] = term;
    __syncthreads();
    if (tid < 32) {
        float v = (tid < 16) ? we[tid] : 0.f;
        #pragma unroll
        for (int o = 8; o; o >>= 1) v += __shfl_down_sync(0xffffffffu, v, o);
        if (tid == 0) {
            double ent_d = __ldcg(&g_ent);
            double com_d = __ldcg(&g_commit);
            float pse          = (float)(ent_d / 65536.0);
            float avg_entropy  = -v;                        // ENT_GAMMA = 1.0
            float entropy_loss = 0.1f * (pse - avg_entropy);
            float commitment   = 0.25f * (float)(com_d / 655360.0);
            out[OUT_SCALARS + 0] = commitment + entropy_loss;  // loss
            out[OUT_SCALARS + 1] = commitment;
            out[OUT_SCALARS + 2] = entropy_loss;
            out[OUT_SCALARS + 3] = pse;
            out[OUT_SCALARS + 4] = avg_entropy;
            g_ent = 0.0;
            g_commit = 0.0;
            g_count = 0u;
        }
    }
    // reset g_avg for the next (graph-replayed) launch
    __syncthreads();
    g_avg[tid] = 0.f;
    g_avg[tid + 512] = 0.f;
}

extern "C" void kernel_launch(void* const* d_in, const int* in_sizes, int n_in,
                              void* d_out, int out_size) {
    const float* z = (const float*)d_in[0];
    float* out = (float*)d_out;
    fused_kernel<<<NBLK, NTHR>>>(z, out);
}